// round 4
// baseline (speedup 1.0000x reference)
#include <cuda_runtime.h>
#include <math.h>

#define Bn 8
#define Cn 2048
#define Dn 64
#define Hn 4
#define Ln 3
#define FFn 256
#define OUTn 10
#define BHn (Bn*Hn)

typedef unsigned long long u64;

__device__ float g_h   [Bn*Cn*Dn];
__device__ float g_q   [Bn*Cn*Dn];
__device__ float g_k   [Bn*Cn*Dn];
__device__ float g_v   [Bn*Cn*Dn];
__device__ float g_qp  [Bn*Cn*Dn];
__device__ float g_kp  [Bn*Cn*Dn];
__device__ float g_attn[Bn*Cn*Dn];
__device__ float g_ff  [Bn*Cn*FFn];
__device__ unsigned g_rowmax[BHn*Cn];
__device__ float g_S   [(size_t)BHn*Cn*Cn];

// ---- f32x2 packed helpers (sm_103a) ----
__device__ __forceinline__ u64 pk(float lo, float hi){
    u64 r; asm("mov.b64 %0,{%1,%2};" : "=l"(r) : "f"(lo), "f"(hi)); return r;
}
__device__ __forceinline__ void upk(u64 v, float& lo, float& hi){
    asm("mov.b64 {%0,%1},%2;" : "=f"(lo), "=f"(hi) : "l"(v));
}
__device__ __forceinline__ u64 mul2(u64 a, u64 b){
    u64 r; asm("mul.rn.f32x2 %0,%1,%2;" : "=l"(r) : "l"(a), "l"(b)); return r;
}
__device__ __forceinline__ u64 fma2(u64 a, u64 b, u64 c){
    u64 r; asm("fma.rn.f32x2 %0,%1,%2,%3;" : "=l"(r) : "l"(a), "l"(b), "l"(c)); return r;
}
__device__ __forceinline__ u64 add2(u64 a, u64 b){
    u64 r; asm("add.rn.f32x2 %0,%1,%2;" : "=l"(r) : "l"(a), "l"(b)); return r;
}
__device__ __forceinline__ u64 dup2(float v){
    unsigned b = __float_as_uint(v);
    return ((u64)b<<32) | (u64)b;
}
__device__ __forceinline__ float rcpf(float x){ float r; asm("rcp.approx.f32 %0,%1;" : "=f"(r):"f"(x)); return r; }
__device__ __forceinline__ float ex2f(float x){ float r; asm("ex2.approx.f32 %0,%1;" : "=f"(r):"f"(x)); return r; }

__device__ __forceinline__ float gelu_f(float v){           // exact (cold paths)
    return 0.5f*v*(1.0f + erff(v*0.70710678118654752f));
}

// packed branch-free gelu on (lo,hi) pair; A&S 7.1.26 erf, abs err <= 1.5e-7
__device__ __forceinline__ u64 gelu2(u64 r2){
    u64 z2  = mul2(r2, dup2(0.70710678118654752f));
    u64 az2 = z2 & 0x7FFFFFFF7FFFFFFFULL;
    u64 w2  = fma2(az2, dup2(0.3275911f), dup2(1.0f));
    float wlo, whi; upk(w2, wlo, whi);
    u64 t2  = pk(rcpf(wlo), rcpf(whi));
    u64 zz2 = mul2(z2, z2);
    u64 ag2 = mul2(zz2, dup2(-1.4426950408889634f));
    float alo, ahi; upk(ag2, alo, ahi);
    u64 e2  = pk(ex2f(alo), ex2f(ahi));
    u64 s2  = fma2(t2, dup2(-1.061405429f), dup2(1.453152027f));
    s2 = fma2(s2, t2, dup2(-1.421413741f));
    s2 = fma2(s2, t2, dup2( 0.284496736f));
    s2 = fma2(s2, t2, dup2(-0.254829592f));
    s2 = mul2(s2, t2);                                   // s2 = -s
    u64 erfa2 = fma2(s2, e2, dup2(1.0f));                // 1 - s*exp(-z^2)  (>=0)
    u64 es2   = erfa2 | (z2 & 0x8000000080000000ULL);    // copysign from z
    u64 hr2   = mul2(r2, dup2(0.5f));
    return fma2(hr2, es2, hr2);                          // 0.5r(1+erf)
}

// ---- float<->monotone-unsigned encoding for atomic max ----
__device__ __forceinline__ unsigned encf(float x){
    unsigned u = __float_as_uint(x);
    return (u & 0x80000000u) ? ~u : (u | 0x80000000u);
}
__device__ __forceinline__ float decf(unsigned e){
    return (e & 0x80000000u) ? __uint_as_float(e ^ 0x80000000u) : __uint_as_float(~e);
}

__global__ void k_zmax(){
    int i = blockIdx.x*blockDim.x + threadIdx.x;
    if (i < BHn*Cn) g_rowmax[i] = 0u;
}

__global__ void k_binding(const float* __restrict__ x, const float* __restrict__ role,
                          const float* __restrict__ fw){
    int idx = blockIdx.x*blockDim.x + threadIdx.x;
    if (idx >= Bn*Cn*Dn) return;
    int dd = idx & 63;
    int bc = idx >> 6;
    int c  = bc & (Cn-1);
    float xl = log1pf(fmaxf(x[bc], 0.0f));
    g_h[idx] = role[c*Dn + dd] * gelu_f(xl * fw[dd]);
}

__global__ void k_qkv(const float* __restrict__ qw, const float* __restrict__ qb,
                      const float* __restrict__ kw, const float* __restrict__ kb,
                      const float* __restrict__ vw, const float* __restrict__ vb){
    __shared__ float hs[4][Dn];
    int r0 = blockIdx.x*4;
    int t  = threadIdx.x;
    for (int i=t; i<4*Dn; i+=64) hs[i>>6][i&63] = g_h[r0*Dn + i];
    __syncthreads();
    int o = t;
    float bq=qb[o], bk=kb[o], bv=vb[o];
    float aq[4]={bq,bq,bq,bq}, ak[4]={bk,bk,bk,bk}, av[4]={bv,bv,bv,bv};
    for (int d=0; d<Dn; d++){
        float wq=qw[o*Dn+d], wk2=kw[o*Dn+d], wv=vw[o*Dn+d];
        #pragma unroll
        for (int r=0;r<4;r++){
            float hh = hs[r][d];
            aq[r]=fmaf(wq ,hh,aq[r]);
            ak[r]=fmaf(wk2,hh,ak[r]);
            av[r]=fmaf(wv ,hh,av[r]);
        }
    }
    #pragma unroll
    for (int r=0;r<4;r++){
        g_q[(r0+r)*Dn+o]=aq[r];
        g_k[(r0+r)*Dn+o]=ak[r];
        g_v[(r0+r)*Dn+o]=av[r];
    }
}

// qp = q @ w1q.T + b1 (b1 folded), kp = k @ w1k.T
__global__ void k_phead(const float* __restrict__ w1l, const float* __restrict__ b1l){
    __shared__ float qs[4][Dn], ks[4][Dn];
    int r0 = blockIdx.x*4;
    int t  = threadIdx.x;
    for (int i=t;i<4*Dn;i+=64){ qs[i>>6][i&63]=g_q[r0*Dn+i]; ks[i>>6][i&63]=g_k[r0*Dn+i]; }
    __syncthreads();
    int o=t, hh=o>>4, ci=o&15;
    float wq[16], wk[16];
    #pragma unroll
    for (int e=0;e<16;e++){ wq[e]=w1l[ci*48+e]; wk[e]=w1l[ci*48+16+e]; }
    float bb = b1l[ci];
    #pragma unroll
    for (int r=0;r<4;r++){
        float aq=bb, ak=0.f;
        #pragma unroll
        for (int e=0;e<16;e++){
            aq = fmaf(qs[r][hh*16+e], wq[e], aq);
            ak = fmaf(ks[r][hh*16+e], wk[e], ak);
        }
        g_qp[(r0+r)*Dn+o]=aq;
        g_kp[(r0+r)*Dn+o]=ak;
    }
}

// hot loop: grid (C/32 j, C/32 i, B*H), 256 threads = 32 i x (8 groups x 4 j)
__global__ void __launch_bounds__(256) k_score(const float* __restrict__ w1l,
                                               const float* __restrict__ w2l,
                                               const float* __restrict__ b2l){
    __shared__ u64 q2s[32][9];
    __shared__ u64 k2s[32][9];
    __shared__ __align__(16) u64 wqk2[16][8];
    __shared__ __align__(16) float qps[32][20];
    __shared__ __align__(16) float kps[32][20];
    __shared__ u64 w2d[16];

    int bh = blockIdx.z; int b = bh>>2; int hh = bh&3;
    int i0 = blockIdx.y<<5, j0 = blockIdx.x<<5;
    int t  = threadIdx.x;

    {
        int t2 = t & 127;
        int row = t2 >> 2, qd = t2 & 3;
        if (t < 128){
            int gidx = (b*Cn + i0 + row)*Dn + hh*16 + qd*4;
            float4 qv  = *(const float4*)(g_q  + gidx);
            float4 qpv = *(const float4*)(g_qp + gidx);
            q2s[row][qd*2+0] = pk(qv.x, qv.y);
            q2s[row][qd*2+1] = pk(qv.z, qv.w);
            *(float4*)&qps[row][qd*4] = qpv;
        } else {
            int gidx = (b*Cn + j0 + row)*Dn + hh*16 + qd*4;
            float4 kv  = *(const float4*)(g_k  + gidx);
            float4 kpv = *(const float4*)(g_kp + gidx);
            k2s[row][qd*2+0] = pk(kv.x, kv.y);
            k2s[row][qd*2+1] = pk(kv.z, kv.w);
            *(float4*)&kps[row][qd*4] = kpv;
        }
        if (t < 64){
            int ci=t>>2, q4=t&3;
            float4 wv = *(const float4*)(w1l + ci*48 + 32 + q4*4);
            wqk2[ci][q4*2+0] = pk(wv.x, wv.y);
            wqk2[ci][q4*2+1] = pk(wv.z, wv.w);
        }
        if (t < 16){ float w = w2l[t]; w2d[t] = pk(w, w); }
    }
    __syncthreads();

    int ti = t>>3;
    int jb = (t&7)<<2;

    u64 q2[8], p2[4][8];
    #pragma unroll
    for (int e=0;e<8;e++) q2[e]=q2s[ti][e];
    #pragma unroll
    for (int jj=0;jj<4;jj++){
        #pragma unroll
        for (int e=0;e<8;e++) p2[jj][e] = mul2(q2[e], k2s[jb+jj][e]);
    }

    u64 acca = dup2(0.0f), accb = dup2(0.0f);   // (jj0,jj1), (jj2,jj3)
    #pragma unroll
    for (int c4=0;c4<4;c4++){
        float4 qp4 = *(float4*)&qps[ti][c4*4];
        float4 kp4[4];
        #pragma unroll
        for (int jj=0;jj<4;jj++) kp4[jj] = *(float4*)&kps[jb+jj][c4*4];
        #pragma unroll
        for (int cc=0;cc<4;cc++){
            int c = c4*4+cc;
            ulonglong2* pw = (ulonglong2*)&wqk2[c][0];
            ulonglong2 wA=pw[0], wB=pw[1], wC=pw[2], wD=pw[3];
            float qpb = (cc==0)?qp4.x:(cc==1)?qp4.y:(cc==2)?qp4.z:qp4.w;
            float r[4];
            #pragma unroll
            for (int jj=0;jj<4;jj++){
                u64 a = mul2(wA.x, p2[jj][0]);
                a = fma2(wA.y, p2[jj][1], a);
                a = fma2(wB.x, p2[jj][2], a);
                a = fma2(wB.y, p2[jj][3], a);
                u64 d = mul2(wC.x, p2[jj][4]);
                d = fma2(wC.y, p2[jj][5], d);
                d = fma2(wD.x, p2[jj][6], d);
                d = fma2(wD.y, p2[jj][7], d);
                u64 s = add2(a, d);
                float slo, shi; upk(s, slo, shi);
                float kpv = (cc==0)?kp4[jj].x:(cc==1)?kp4[jj].y:(cc==2)?kp4[jj].z:kp4[jj].w;
                r[jj] = (slo + shi) + (qpb + kpv);
            }
            u64 w2c = w2d[c];
            u64 ga = gelu2(pk(r[0], r[1]));
            u64 gb = gelu2(pk(r[2], r[3]));
            acca = fma2(ga, w2c, acca);
            accb = fma2(gb, w2c, accb);
        }
    }
    float b2 = __ldg(b2l);
    float a0,a1,a2,a3;
    upk(acca, a0, a1); upk(accb, a2, a3);
    float s0 = 0.25f*(a0+b2), s1 = 0.25f*(a1+b2);
    float s2 = 0.25f*(a2+b2), s3 = 0.25f*(a3+b2);
    size_t off = ((size_t)bh*Cn + (i0+ti))*Cn + j0 + jb;
    *(float4*)(g_S + off) = make_float4(s0,s1,s2,s3);

    // fused row max (exact) over the 32-wide j tile, 8 threads per row
    float m = fmaxf(fmaxf(s0,s1), fmaxf(s2,s3));
    m = fmaxf(m, __shfl_xor_sync(0xffffffffu, m, 1, 8));
    m = fmaxf(m, __shfl_xor_sync(0xffffffffu, m, 2, 8));
    m = fmaxf(m, __shfl_xor_sync(0xffffffffu, m, 4, 8));
    if ((t & 7) == 0) atomicMax(&g_rowmax[bh*Cn + i0 + ti], encf(m));
}

// softmax + A@V fused (single pass; max from g_rowmax): grid (C/64, B*H)
__global__ void __launch_bounds__(256) k_softav(){
    int bh=blockIdx.y, b=bh>>2, hh=bh&3;
    int i0=blockIdx.x<<6;
    int t=threadIdx.x, li=t>>2, g=t&3;
    const float* sr = g_S + ((size_t)bh*Cn + i0 + li)*Cn;
    float m = decf(g_rowmax[bh*Cn + i0 + li]);

    __shared__ float red[64][4];
    __shared__ float vt[64][16];
    __shared__ float et[64][65];
    float a0=0.f,a1=0.f,a2=0.f,a3=0.f, sacc=0.f;

    for (int jt=0;jt<Cn/64;jt++){
        __syncthreads();
        {
            int row=t>>2, qd=t&3;
            float4 vv = *(const float4*)(g_v + ((size_t)(b*Cn) + jt*64 + row)*Dn + hh*16 + qd*4);
            *(float4*)&vt[row][qd*4]=vv;
        }
        {
            const float* sp = sr + jt*64 + g*16;
            #pragma unroll
            for (int kk=0;kk<16;kk+=4){
                float4 s4=*(const float4*)(sp+kk);
                float e0=__expf(s4.x-m), e1=__expf(s4.y-m);
                float e2=__expf(s4.z-m), e3=__expf(s4.w-m);
                et[li][g*16+kk+0]=e0; et[li][g*16+kk+1]=e1;
                et[li][g*16+kk+2]=e2; et[li][g*16+kk+3]=e3;
                sacc += (e0+e1)+(e2+e3);
            }
        }
        __syncthreads();
        #pragma unroll 4
        for (int jj=0;jj<64;jj++){
            float ev=et[li][jj];
            float4 vv=*(const float4*)&vt[jj][g*4];
            a0=fmaf(ev,vv.x,a0); a1=fmaf(ev,vv.y,a1);
            a2=fmaf(ev,vv.z,a2); a3=fmaf(ev,vv.w,a3);
        }
    }
    __syncthreads();
    red[li][g]=sacc; __syncthreads();
    float inv = 1.0f/(red[li][0]+red[li][1]+red[li][2]+red[li][3]);
    *(float4*)(g_attn + ((size_t)(b*Cn)+i0+li)*Dn + hh*16 + g*4)
        = make_float4(a0*inv,a1*inv,a2*inv,a3*inv);
}

template<int IN>
__global__ void k_lin_res_ln(const float* __restrict__ W, const float* __restrict__ bias,
                             const float* __restrict__ gamma, const float* __restrict__ beta){
    __shared__ float xs[4][IN];
    __shared__ float vals[4][64];
    __shared__ float stats[4][2];
    int r0=blockIdx.x*4, t=threadIdx.x;
    const float* src = (IN==64)? g_attn : g_ff;
    for (int i=t;i<4*IN;i+=64) xs[i/IN][i%IN] = src[r0*IN+i];
    __syncthreads();
    int o=t;
    float bb=bias[o];
    float acc[4]={bb,bb,bb,bb};
    for (int d=0;d<IN;d++){
        float w=W[o*IN+d];
        #pragma unroll
        for (int r=0;r<4;r++) acc[r]=fmaf(w,xs[r][d],acc[r]);
    }
    float val[4];
    #pragma unroll
    for (int r=0;r<4;r++){ val[r]=acc[r]+g_h[(r0+r)*Dn+o]; vals[r][o]=val[r]; }
    __syncthreads();
    int wr=t>>5, lane=t&31;
    #pragma unroll
    for (int rr2=0; rr2<2; rr2++){
        int rrow = wr*2+rr2;
        float v1=vals[rrow][lane], v2=vals[rrow][lane+32];
        float s=v1+v2, q=fmaf(v1,v1,v2*v2);
        #pragma unroll
        for (int off2=16; off2; off2>>=1){
            s += __shfl_down_sync(0xffffffffu, s, off2);
            q += __shfl_down_sync(0xffffffffu, q, off2);
        }
        if (lane==0){
            float mean=s*(1.0f/64.0f);
            float var = q*(1.0f/64.0f) - mean*mean;
            stats[rrow][0]=mean; stats[rrow][1]=rsqrtf(var+1e-5f);
        }
    }
    __syncthreads();
    float gm=gamma[o], bt=beta[o];
    #pragma unroll
    for (int r=0;r<4;r++)
        g_h[(r0+r)*Dn+o] = (val[r]-stats[r][0])*stats[r][1]*gm + bt;
}

__global__ void k_ffn1(const float* __restrict__ W, const float* __restrict__ bias){
    __shared__ float hs[4][Dn];
    int r0=blockIdx.x*4, t=threadIdx.x;
    hs[t>>6][t&63]=g_h[r0*Dn+t];
    __syncthreads();
    int o=t;
    float bb=bias[o];
    float acc[4]={bb,bb,bb,bb};
    for (int d=0;d<Dn;d++){
        float w=W[o*Dn+d];
        #pragma unroll
        for (int r=0;r<4;r++) acc[r]=fmaf(w,hs[r][d],acc[r]);
    }
    #pragma unroll
    for (int r=0;r<4;r++) g_ff[(r0+r)*FFn+o]=gelu_f(acc[r]);
}

__global__ void __launch_bounds__(256) k_readout(const float* __restrict__ tq,
        const float* __restrict__ hw, const float* __restrict__ hb, float* __restrict__ out){
    int b=blockIdx.x, t=threadIdx.x;
    __shared__ float ssm[Cn];
    __shared__ float tqs[Dn];
    __shared__ float red[256];
    __shared__ float pool[4][64];
    if (t<64) tqs[t]=tq[t];
    __syncthreads();
    for (int c=t;c<Cn;c+=256){
        const float* hr=g_h+((size_t)b*Cn+c)*Dn;
        float a=0.f;
        #pragma unroll
        for (int d=0;d<Dn;d++) a=fmaf(hr[d],tqs[d],a);
        ssm[c]=a*0.125f;
    }
    __syncthreads();
    float m=-3e38f;
    for (int c=t;c<Cn;c+=256) m=fmaxf(m,ssm[c]);
    red[t]=m; __syncthreads();
    for (int s2=128;s2;s2>>=1){ if(t<s2) red[t]=fmaxf(red[t],red[t+s2]); __syncthreads(); }
    m=red[0]; __syncthreads();
    float sacc=0.f;
    for (int c=t;c<Cn;c+=256){ float e=__expf(ssm[c]-m); ssm[c]=e; sacc+=e; }
    red[t]=sacc; __syncthreads();
    for (int s2=128;s2;s2>>=1){ if(t<s2) red[t]+=red[t+s2]; __syncthreads(); }
    float stot=red[0];
    __syncthreads();
    int dd=t&63, cg=t>>6;
    float acc=0.f;
    for (int c=cg*512; c<cg*512+512; c++)
        acc=fmaf(ssm[c], g_h[((size_t)b*Cn+c)*Dn+dd], acc);
    pool[cg][dd]=acc; __syncthreads();
    if (t<64) red[t]=(pool[0][t]+pool[1][t]+pool[2][t]+pool[3][t])/stot;
    __syncthreads();
    if (t<OUTn){
        float a=hb[t];
        #pragma unroll
        for (int d=0;d<Dn;d++) a=fmaf(red[d],hw[t*Dn+d],a);
        out[b*OUTn+t]=a;
    }
}

extern "C" void kernel_launch(void* const* d_in, const int* in_sizes, int n_in,
                              void* d_out, int out_size){
    (void)in_sizes; (void)n_in; (void)out_size;
    const float* x   =(const float*)d_in[0];
    const float* role=(const float*)d_in[1];
    const float* fw  =(const float*)d_in[2];
    const float* qw  =(const float*)d_in[3];  const float* qb =(const float*)d_in[4];
    const float* kw  =(const float*)d_in[5];  const float* kb =(const float*)d_in[6];
    const float* vw  =(const float*)d_in[7];  const float* vb =(const float*)d_in[8];
    const float* w1  =(const float*)d_in[9];  const float* b1 =(const float*)d_in[10];
    const float* w2  =(const float*)d_in[11]; const float* b2 =(const float*)d_in[12];
    const float* ow  =(const float*)d_in[13]; const float* ob =(const float*)d_in[14];
    const float* l1g =(const float*)d_in[15]; const float* l1b=(const float*)d_in[16];
    const float* f1w =(const float*)d_in[17]; const float* f1b=(const float*)d_in[18];
    const float* f2w =(const float*)d_in[19]; const float* f2b=(const float*)d_in[20];
    const float* l2g =(const float*)d_in[21]; const float* l2b=(const float*)d_in[22];
    const float* tq  =(const float*)d_in[23];
    const float* hw  =(const float*)d_in[24]; const float* hb =(const float*)d_in[25];
    float* out = (float*)d_out;

    int rows = Bn*Cn;
    k_binding<<<(Bn*Cn*Dn+255)/256,256>>>(x, role, fw);
    for (int l=0; l<Ln; l++){
        k_qkv  <<<rows/4,64>>>(qw+l*Dn*Dn, qb+l*Dn, kw+l*Dn*Dn, kb+l*Dn, vw+l*Dn*Dn, vb+l*Dn);
        k_phead<<<rows/4,64>>>(w1+l*16*48, b1+l*16);
        k_zmax <<<(BHn*Cn+255)/256,256>>>();
        dim3 gs(Cn/32, Cn/32, BHn);
        k_score<<<gs,256>>>(w1+l*16*48, w2+l*16, b2+l);
        dim3 ga(Cn/64, BHn);
        k_softav<<<ga,256>>>();
        k_lin_res_ln<64> <<<rows/4,64>>>(ow+l*Dn*Dn, ob+l*Dn, l1g+l*Dn, l1b+l*Dn);
        k_ffn1<<<rows/4,256>>>(f1w+l*FFn*Dn, f1b+l*FFn);
        k_lin_res_ln<256><<<rows/4,64>>>(f2w+l*Dn*FFn, f2b+l*Dn, l2g+l*Dn, l2b+l*Dn);
    }
    k_readout<<<Bn,256>>>(tq, hw, hb, out);
}

// round 5
// speedup vs baseline: 1.3069x; 1.3069x over previous
#include <cuda_runtime.h>
#include <math.h>

#define Bn 8
#define Cn 2048
#define Dn 64
#define Hn 4
#define Ln 3
#define FFn 256
#define OUTn 10
#define BHn (Bn*Hn)

typedef unsigned long long u64;

__device__ float g_h   [Bn*Cn*Dn];
__device__ float g_q   [Bn*Cn*Dn];
__device__ float g_k   [Bn*Cn*Dn];
__device__ float g_v   [Bn*Cn*Dn];
__device__ float g_qp  [Bn*Cn*Dn];
__device__ float g_kp  [Bn*Cn*Dn];
__device__ float g_attn[Bn*Cn*Dn];
__device__ float g_ff  [Bn*Cn*FFn];
__device__ unsigned g_rowmax[BHn*Cn];
__device__ float g_S   [(size_t)BHn*Cn*Cn];

// ---- f32x2 packed helpers (sm_103a) ----
__device__ __forceinline__ u64 pk(float lo, float hi){
    u64 r; asm("mov.b64 %0,{%1,%2};" : "=l"(r) : "f"(lo), "f"(hi)); return r;
}
__device__ __forceinline__ void upk(u64 v, float& lo, float& hi){
    asm("mov.b64 {%0,%1},%2;" : "=f"(lo), "=f"(hi) : "l"(v));
}
__device__ __forceinline__ u64 mul2(u64 a, u64 b){
    u64 r; asm("mul.rn.f32x2 %0,%1,%2;" : "=l"(r) : "l"(a), "l"(b)); return r;
}
__device__ __forceinline__ u64 fma2(u64 a, u64 b, u64 c){
    u64 r; asm("fma.rn.f32x2 %0,%1,%2,%3;" : "=l"(r) : "l"(a), "l"(b), "l"(c)); return r;
}
__device__ __forceinline__ u64 add2(u64 a, u64 b){
    u64 r; asm("add.rn.f32x2 %0,%1,%2;" : "=l"(r) : "l"(a), "l"(b)); return r;
}
__device__ __forceinline__ u64 dup2(float v){
    unsigned b = __float_as_uint(v);
    return ((u64)b<<32) | (u64)b;
}
__device__ __forceinline__ float rcpf(float x){ float r; asm("rcp.approx.f32 %0,%1;" : "=f"(r):"f"(x)); return r; }
__device__ __forceinline__ float ex2f(float x){ float r; asm("ex2.approx.f32 %0,%1;" : "=f"(r):"f"(x)); return r; }

__device__ __forceinline__ float gelu_f(float v){           // exact (cold paths)
    return 0.5f*v*(1.0f + erff(v*0.70710678118654752f));
}

// packed branch-free gelu on (lo,hi) pair; A&S 7.1.26 erf, abs err <= 1.5e-7
__device__ __forceinline__ u64 gelu2(u64 r2){
    u64 z2  = mul2(r2, dup2(0.70710678118654752f));
    u64 az2 = z2 & 0x7FFFFFFF7FFFFFFFULL;
    u64 w2  = fma2(az2, dup2(0.3275911f), dup2(1.0f));
    float wlo, whi; upk(w2, wlo, whi);
    u64 t2  = pk(rcpf(wlo), rcpf(whi));
    u64 zz2 = mul2(z2, z2);
    u64 ag2 = mul2(zz2, dup2(-1.4426950408889634f));
    float alo, ahi; upk(ag2, alo, ahi);
    u64 e2  = pk(ex2f(alo), ex2f(ahi));
    u64 s2  = fma2(t2, dup2(-1.061405429f), dup2(1.453152027f));
    s2 = fma2(s2, t2, dup2(-1.421413741f));
    s2 = fma2(s2, t2, dup2( 0.284496736f));
    s2 = fma2(s2, t2, dup2(-0.254829592f));
    s2 = mul2(s2, t2);                                   // s2 = -s
    u64 erfa2 = fma2(s2, e2, dup2(1.0f));                // 1 - s*exp(-z^2)  (>=0)
    u64 es2   = erfa2 | (z2 & 0x8000000080000000ULL);    // copysign from z
    u64 hr2   = mul2(r2, dup2(0.5f));
    return fma2(hr2, es2, hr2);                          // 0.5r(1+erf)
}

// ---- float<->monotone-unsigned encoding for atomic max ----
__device__ __forceinline__ unsigned encf(float x){
    unsigned u = __float_as_uint(x);
    return (u & 0x80000000u) ? ~u : (u | 0x80000000u);
}
__device__ __forceinline__ float decf(unsigned e){
    return (e & 0x80000000u) ? __uint_as_float(e ^ 0x80000000u) : __uint_as_float(~e);
}

__global__ void k_zmax(){
    int i = blockIdx.x*blockDim.x + threadIdx.x;
    if (i < BHn*Cn) g_rowmax[i] = 0u;
}

__global__ void k_binding(const float* __restrict__ x, const float* __restrict__ role,
                          const float* __restrict__ fw){
    int idx = blockIdx.x*blockDim.x + threadIdx.x;
    if (idx >= Bn*Cn*Dn) return;
    int dd = idx & 63;
    int bc = idx >> 6;
    int c  = bc & (Cn-1);
    float xl = log1pf(fmaxf(x[bc], 0.0f));
    g_h[idx] = role[c*Dn + dd] * gelu_f(xl * fw[dd]);
}

__global__ void k_qkv(const float* __restrict__ qw, const float* __restrict__ qb,
                      const float* __restrict__ kw, const float* __restrict__ kb,
                      const float* __restrict__ vw, const float* __restrict__ vb){
    __shared__ float hs[4][Dn];
    int r0 = blockIdx.x*4;
    int t  = threadIdx.x;
    for (int i=t; i<4*Dn; i+=64) hs[i>>6][i&63] = g_h[r0*Dn + i];
    __syncthreads();
    int o = t;
    float bq=qb[o], bk=kb[o], bv=vb[o];
    float aq[4]={bq,bq,bq,bq}, ak[4]={bk,bk,bk,bk}, av[4]={bv,bv,bv,bv};
    for (int d=0; d<Dn; d++){
        float wq=qw[o*Dn+d], wk2=kw[o*Dn+d], wv=vw[o*Dn+d];
        #pragma unroll
        for (int r=0;r<4;r++){
            float hh = hs[r][d];
            aq[r]=fmaf(wq ,hh,aq[r]);
            ak[r]=fmaf(wk2,hh,ak[r]);
            av[r]=fmaf(wv ,hh,av[r]);
        }
    }
    #pragma unroll
    for (int r=0;r<4;r++){
        g_q[(r0+r)*Dn+o]=aq[r];
        g_k[(r0+r)*Dn+o]=ak[r];
        g_v[(r0+r)*Dn+o]=av[r];
    }
}

// qp = q @ w1q.T + b1 (b1 folded), kp = k @ w1k.T
__global__ void k_phead(const float* __restrict__ w1l, const float* __restrict__ b1l){
    __shared__ float qs[4][Dn], ks[4][Dn];
    int r0 = blockIdx.x*4;
    int t  = threadIdx.x;
    for (int i=t;i<4*Dn;i+=64){ qs[i>>6][i&63]=g_q[r0*Dn+i]; ks[i>>6][i&63]=g_k[r0*Dn+i]; }
    __syncthreads();
    int o=t, hh=o>>4, ci=o&15;
    float wq[16], wk[16];
    #pragma unroll
    for (int e=0;e<16;e++){ wq[e]=w1l[ci*48+e]; wk[e]=w1l[ci*48+16+e]; }
    float bb = b1l[ci];
    #pragma unroll
    for (int r=0;r<4;r++){
        float aq=bb, ak=0.f;
        #pragma unroll
        for (int e=0;e<16;e++){
            aq = fmaf(qs[r][hh*16+e], wq[e], aq);
            ak = fmaf(ks[r][hh*16+e], wk[e], ak);
        }
        g_qp[(r0+r)*Dn+o]=aq;
        g_kp[(r0+r)*Dn+o]=ak;
    }
}

// hot loop: grid (C/32 j, C/32 i, B*H), 256 threads = 32 i x 8 j-groups (4 j each)
// j-pair-packed layout: all dot math runs as f32x2 with lanes = (j_even, j_odd).
__global__ void __launch_bounds__(256) k_score(const float* __restrict__ w1l,
                                               const float* __restrict__ w2l,
                                               const float* __restrict__ b2l){
    __shared__ float qs [32][17];
    __shared__ float ks [32][17];
    __shared__ __align__(16) float qps[32][20];
    __shared__ float kps[32][17];
    __shared__ __align__(16) u64 k2t[16][18];   // k2t[e][jp] = (k[2jp][e], k[2jp+1][e])
    __shared__ __align__(16) u64 kpt[16][18];   // kpt[c][jp] = (kp[2jp][c], kp[2jp+1][c])
    __shared__ __align__(16) u64 wd [16][18];   // wd[c][e] = (w,w)
    __shared__ u64 w2d[16];

    int bh = blockIdx.z; int b = bh>>2; int hh = bh&3;
    int i0 = blockIdx.y<<5, j0 = blockIdx.x<<5;
    int t  = threadIdx.x;

    // phase 1: coalesced staging + weight dup
    {
        int t2 = t & 127;
        int row = t2 >> 2, q4 = t2 & 3;
        if (t < 128){
            int gidx = (b*Cn + i0 + row)*Dn + hh*16 + q4*4;
            float4 qv  = *(const float4*)(g_q  + gidx);
            float4 qpv = *(const float4*)(g_qp + gidx);
            qs[row][q4*4+0]=qv.x; qs[row][q4*4+1]=qv.y;
            qs[row][q4*4+2]=qv.z; qs[row][q4*4+3]=qv.w;
            *(float4*)&qps[row][q4*4] = qpv;
        } else {
            int gidx = (b*Cn + j0 + row)*Dn + hh*16 + q4*4;
            float4 kv  = *(const float4*)(g_k  + gidx);
            float4 kpv = *(const float4*)(g_kp + gidx);
            ks[row][q4*4+0]=kv.x; ks[row][q4*4+1]=kv.y;
            ks[row][q4*4+2]=kv.z; ks[row][q4*4+3]=kv.w;
            kps[row][q4*4+0]=kpv.x; kps[row][q4*4+1]=kpv.y;
            kps[row][q4*4+2]=kpv.z; kps[row][q4*4+3]=kpv.w;
        }
        int c = t>>4, e = t&15;
        float wv = w1l[c*48 + 32 + e];
        wd[c][e] = pk(wv, wv);
        if (t < 16) w2d[t] = pk(w2l[t], w2l[t]);
    }
    __syncthreads();
    // phase 2: build j-pair-packed transposed tiles
    {
        int e = t>>4, jp = t&15;
        k2t[e][jp] = pk(ks [2*jp][e], ks [2*jp+1][e]);
        kpt[e][jp] = pk(kps[2*jp][e], kps[2*jp+1][e]);
    }
    __syncthreads();

    int ti  = t>>3;          // i row 0..31
    int jpb = (t&7)*2;       // jp pair base -> j = 4*(t&7) .. +3

    u64 pe0[16], pe1[16];
    #pragma unroll
    for (int e=0;e<16;e++){
        float qf = qs[ti][e];
        u64 q2 = pk(qf, qf);
        ulonglong2 kk = *(ulonglong2*)&k2t[e][jpb];
        pe0[e] = mul2(q2, kk.x);
        pe1[e] = mul2(q2, kk.y);
    }

    u64 acc0 = dup2(0.0f), acc1 = dup2(0.0f);
    #pragma unroll
    for (int c=0;c<16;c++){
        ulonglong2 kp2 = *(ulonglong2*)&kpt[c][jpb];
        float qpf = qps[ti][c];
        u64 qpd = pk(qpf, qpf);
        u64 r0 = add2(qpd, kp2.x);
        u64 r1 = add2(qpd, kp2.y);
        ulonglong2* wp = (ulonglong2*)&wd[c][0];
        #pragma unroll
        for (int e4=0;e4<8;e4++){
            ulonglong2 wv = wp[e4];
            r0 = fma2(wv.x, pe0[2*e4+0], r0);
            r1 = fma2(wv.x, pe1[2*e4+0], r1);
            r0 = fma2(wv.y, pe0[2*e4+1], r0);
            r1 = fma2(wv.y, pe1[2*e4+1], r1);
        }
        u64 w2c = w2d[c];
        acc0 = fma2(gelu2(r0), w2c, acc0);
        acc1 = fma2(gelu2(r1), w2c, acc1);
    }

    float b2 = __ldg(b2l);
    float a0,a1,a2,a3;
    upk(acc0, a0, a1); upk(acc1, a2, a3);
    float s0 = 0.25f*(a0+b2), s1 = 0.25f*(a1+b2);
    float s2 = 0.25f*(a2+b2), s3 = 0.25f*(a3+b2);
    size_t off = ((size_t)bh*Cn + (i0+ti))*Cn + j0 + jpb*2;
    *(float4*)(g_S + off) = make_float4(s0,s1,s2,s3);

    // fused exact row max over the 32-wide j tile (8 threads per row)
    float m = fmaxf(fmaxf(s0,s1), fmaxf(s2,s3));
    m = fmaxf(m, __shfl_xor_sync(0xffffffffu, m, 1, 8));
    m = fmaxf(m, __shfl_xor_sync(0xffffffffu, m, 2, 8));
    m = fmaxf(m, __shfl_xor_sync(0xffffffffu, m, 4, 8));
    if ((t & 7) == 0) atomicMax(&g_rowmax[bh*Cn + i0 + ti], encf(m));
}

// softmax + A@V fused (single pass; max from g_rowmax): grid (C/64, B*H)
__global__ void __launch_bounds__(256) k_softav(){
    int bh=blockIdx.y, b=bh>>2, hh=bh&3;
    int i0=blockIdx.x<<6;
    int t=threadIdx.x, li=t>>2, g=t&3;
    const float* sr = g_S + ((size_t)bh*Cn + i0 + li)*Cn;
    float m = decf(g_rowmax[bh*Cn + i0 + li]);

    __shared__ float red[64][4];
    __shared__ float vt[64][16];
    __shared__ float et[64][65];
    float a0=0.f,a1=0.f,a2=0.f,a3=0.f, sacc=0.f;

    for (int jt=0;jt<Cn/64;jt++){
        __syncthreads();
        {
            int row=t>>2, qd=t&3;
            float4 vv = *(const float4*)(g_v + ((size_t)(b*Cn) + jt*64 + row)*Dn + hh*16 + qd*4);
            *(float4*)&vt[row][qd*4]=vv;
        }
        {
            const float* sp = sr + jt*64 + g*16;
            #pragma unroll
            for (int kk=0;kk<16;kk+=4){
                float4 s4=*(const float4*)(sp+kk);
                float e0=__expf(s4.x-m), e1=__expf(s4.y-m);
                float e2=__expf(s4.z-m), e3=__expf(s4.w-m);
                et[li][g*16+kk+0]=e0; et[li][g*16+kk+1]=e1;
                et[li][g*16+kk+2]=e2; et[li][g*16+kk+3]=e3;
                sacc += (e0+e1)+(e2+e3);
            }
        }
        __syncthreads();
        #pragma unroll 4
        for (int jj=0;jj<64;jj++){
            float ev=et[li][jj];
            float4 vv=*(const float4*)&vt[jj][g*4];
            a0=fmaf(ev,vv.x,a0); a1=fmaf(ev,vv.y,a1);
            a2=fmaf(ev,vv.z,a2); a3=fmaf(ev,vv.w,a3);
        }
    }
    __syncthreads();
    red[li][g]=sacc; __syncthreads();
    float inv = 1.0f/(red[li][0]+red[li][1]+red[li][2]+red[li][3]);
    *(float4*)(g_attn + ((size_t)(b*Cn)+i0+li)*Dn + hh*16 + g*4)
        = make_float4(a0*inv,a1*inv,a2*inv,a3*inv);
}

template<int IN>
__global__ void k_lin_res_ln(const float* __restrict__ W, const float* __restrict__ bias,
                             const float* __restrict__ gamma, const float* __restrict__ beta){
    __shared__ float xs[4][IN];
    __shared__ float vals[4][64];
    __shared__ float stats[4][2];
    int r0=blockIdx.x*4, t=threadIdx.x;
    const float* src = (IN==64)? g_attn : g_ff;
    for (int i=t;i<4*IN;i+=64) xs[i/IN][i%IN] = src[r0*IN+i];
    __syncthreads();
    int o=t;
    float bb=bias[o];
    float acc[4]={bb,bb,bb,bb};
    for (int d=0;d<IN;d++){
        float w=W[o*IN+d];
        #pragma unroll
        for (int r=0;r<4;r++) acc[r]=fmaf(w,xs[r][d],acc[r]);
    }
    float val[4];
    #pragma unroll
    for (int r=0;r<4;r++){ val[r]=acc[r]+g_h[(r0+r)*Dn+o]; vals[r][o]=val[r]; }
    __syncthreads();
    int wr=t>>5, lane=t&31;
    #pragma unroll
    for (int rr2=0; rr2<2; rr2++){
        int rrow = wr*2+rr2;
        float v1=vals[rrow][lane], v2=vals[rrow][lane+32];
        float s=v1+v2, q=fmaf(v1,v1,v2*v2);
        #pragma unroll
        for (int off2=16; off2; off2>>=1){
            s += __shfl_down_sync(0xffffffffu, s, off2);
            q += __shfl_down_sync(0xffffffffu, q, off2);
        }
        if (lane==0){
            float mean=s*(1.0f/64.0f);
            float var = q*(1.0f/64.0f) - mean*mean;
            stats[rrow][0]=mean; stats[rrow][1]=rsqrtf(var+1e-5f);
        }
    }
    __syncthreads();
    float gm=gamma[o], bt=beta[o];
    #pragma unroll
    for (int r=0;r<4;r++)
        g_h[(r0+r)*Dn+o] = (val[r]-stats[r][0])*stats[r][1]*gm + bt;
}

__global__ void k_ffn1(const float* __restrict__ W, const float* __restrict__ bias){
    __shared__ float hs[4][Dn];
    int r0=blockIdx.x*4, t=threadIdx.x;
    hs[t>>6][t&63]=g_h[r0*Dn+t];
    __syncthreads();
    int o=t;
    float bb=bias[o];
    float acc[4]={bb,bb,bb,bb};
    for (int d=0;d<Dn;d++){
        float w=W[o*Dn+d];
        #pragma unroll
        for (int r=0;r<4;r++) acc[r]=fmaf(w,hs[r][d],acc[r]);
    }
    #pragma unroll
    for (int r=0;r<4;r++) g_ff[(r0+r)*FFn+o]=gelu_f(acc[r]);
}

__global__ void __launch_bounds__(256) k_readout(const float* __restrict__ tq,
        const float* __restrict__ hw, const float* __restrict__ hb, float* __restrict__ out){
    int b=blockIdx.x, t=threadIdx.x;
    __shared__ float ssm[Cn];
    __shared__ float tqs[Dn];
    __shared__ float red[256];
    __shared__ float pool[4][64];
    if (t<64) tqs[t]=tq[t];
    __syncthreads();
    for (int c=t;c<Cn;c+=256){
        const float* hr=g_h+((size_t)b*Cn+c)*Dn;
        float a=0.f;
        #pragma unroll
        for (int d=0;d<Dn;d++) a=fmaf(hr[d],tqs[d],a);
        ssm[c]=a*0.125f;
    }
    __syncthreads();
    float m=-3e38f;
    for (int c=t;c<Cn;c+=256) m=fmaxf(m,ssm[c]);
    red[t]=m; __syncthreads();
    for (int s2=128;s2;s2>>=1){ if(t<s2) red[t]=fmaxf(red[t],red[t+s2]); __syncthreads(); }
    m=red[0]; __syncthreads();
    float sacc=0.f;
    for (int c=t;c<Cn;c+=256){ float e=__expf(ssm[c]-m); ssm[c]=e; sacc+=e; }
    red[t]=sacc; __syncthreads();
    for (int s2=128;s2;s2>>=1){ if(t<s2) red[t]+=red[t+s2]; __syncthreads(); }
    float stot=red[0];
    __syncthreads();
    int dd=t&63, cg=t>>6;
    float acc=0.f;
    for (int c=cg*512; c<cg*512+512; c++)
        acc=fmaf(ssm[c], g_h[((size_t)b*Cn+c)*Dn+dd], acc);
    pool[cg][dd]=acc; __syncthreads();
    if (t<64) red[t]=(pool[0][t]+pool[1][t]+pool[2][t]+pool[3][t])/stot;
    __syncthreads();
    if (t<OUTn){
        float a=hb[t];
        #pragma unroll
        for (int d=0;d<Dn;d++) a=fmaf(red[d],hw[t*Dn+d],a);
        out[b*OUTn+t]=a;
    }
}

extern "C" void kernel_launch(void* const* d_in, const int* in_sizes, int n_in,
                              void* d_out, int out_size){
    (void)in_sizes; (void)n_in; (void)out_size;
    const float* x   =(const float*)d_in[0];
    const float* role=(const float*)d_in[1];
    const float* fw  =(const float*)d_in[2];
    const float* qw  =(const float*)d_in[3];  const float* qb =(const float*)d_in[4];
    const float* kw  =(const float*)d_in[5];  const float* kb =(const float*)d_in[6];
    const float* vw  =(const float*)d_in[7];  const float* vb =(const float*)d_in[8];
    const float* w1  =(const float*)d_in[9];  const float* b1 =(const float*)d_in[10];
    const float* w2  =(const float*)d_in[11]; const float* b2 =(const float*)d_in[12];
    const float* ow  =(const float*)d_in[13]; const float* ob =(const float*)d_in[14];
    const float* l1g =(const float*)d_in[15]; const float* l1b=(const float*)d_in[16];
    const float* f1w =(const float*)d_in[17]; const float* f1b=(const float*)d_in[18];
    const float* f2w =(const float*)d_in[19]; const float* f2b=(const float*)d_in[20];
    const float* l2g =(const float*)d_in[21]; const float* l2b=(const float*)d_in[22];
    const float* tq  =(const float*)d_in[23];
    const float* hw  =(const float*)d_in[24]; const float* hb =(const float*)d_in[25];
    float* out = (float*)d_out;

    int rows = Bn*Cn;
    k_binding<<<(Bn*Cn*Dn+255)/256,256>>>(x, role, fw);
    for (int l=0; l<Ln; l++){
        k_qkv  <<<rows/4,64>>>(qw+l*Dn*Dn, qb+l*Dn, kw+l*Dn*Dn, kb+l*Dn, vw+l*Dn*Dn, vb+l*Dn);
        k_phead<<<rows/4,64>>>(w1+l*16*48, b1+l*16);
        k_zmax <<<(BHn*Cn+255)/256,256>>>();
        dim3 gs(Cn/32, Cn/32, BHn);
        k_score<<<gs,256>>>(w1+l*16*48, w2+l*16, b2+l);
        dim3 ga(Cn/64, BHn);
        k_softav<<<ga,256>>>();
        k_lin_res_ln<64> <<<rows/4,64>>>(ow+l*Dn*Dn, ob+l*Dn, l1g+l*Dn, l1b+l*Dn);
        k_ffn1<<<rows/4,256>>>(f1w+l*FFn*Dn, f1b+l*FFn);
        k_lin_res_ln<256><<<rows/4,64>>>(f2w+l*Dn*FFn, f2b+l*Dn, l2g+l*Dn, l2b+l*Dn);
    }
    k_readout<<<Bn,256>>>(tq, hw, hb, out);
}

// round 7
// speedup vs baseline: 1.5398x; 1.1782x over previous
#include <cuda_runtime.h>
#include <math.h>

#define Bn 8
#define Cn 2048
#define Dn 64
#define Hn 4
#define Ln 3
#define FFn 256
#define OUTn 10
#define BHn (Bn*Hn)

typedef unsigned long long u64;

__device__ float g_h   [Bn*Cn*Dn];
__device__ float g_q   [Bn*Cn*Dn];
__device__ float g_k   [Bn*Cn*Dn];
__device__ float g_v   [Bn*Cn*Dn];
__device__ float g_qp  [Bn*Cn*Dn];
__device__ float g_kp  [Bn*Cn*Dn];
__device__ float g_attn[Bn*Cn*Dn];
__device__ float g_ff  [Bn*Cn*FFn];
__device__ unsigned g_rowmax[BHn*Cn];
__device__ float g_S   [(size_t)BHn*Cn*Cn];

// transposed weights (built once per call by k_transW)
__device__ float g_qwT [Ln*Dn*Dn];
__device__ float g_kwT [Ln*Dn*Dn];
__device__ float g_vwT [Ln*Dn*Dn];
__device__ float g_owT [Ln*Dn*Dn];
__device__ float g_f1wT[Ln*Dn*FFn];   // [l][d][o] o=256
__device__ float g_f2wT[Ln*FFn*Dn];   // [l][d][o] o=64

// ---- f32x2 packed helpers (sm_103a) ----
__device__ __forceinline__ u64 pk(float lo, float hi){
    u64 r; asm("mov.b64 %0,{%1,%2};" : "=l"(r) : "f"(lo), "f"(hi)); return r;
}
__device__ __forceinline__ void upk(u64 v, float& lo, float& hi){
    asm("mov.b64 {%0,%1},%2;" : "=f"(lo), "=f"(hi) : "l"(v));
}
__device__ __forceinline__ u64 mul2(u64 a, u64 b){
    u64 r; asm("mul.rn.f32x2 %0,%1,%2;" : "=l"(r) : "l"(a), "l"(b)); return r;
}
__device__ __forceinline__ u64 fma2(u64 a, u64 b, u64 c){
    u64 r; asm("fma.rn.f32x2 %0,%1,%2,%3;" : "=l"(r) : "l"(a), "l"(b), "l"(c)); return r;
}
__device__ __forceinline__ u64 add2(u64 a, u64 b){
    u64 r; asm("add.rn.f32x2 %0,%1,%2;" : "=l"(r) : "l"(a), "l"(b)); return r;
}
__device__ __forceinline__ u64 dup2(float v){
    unsigned b = __float_as_uint(v);
    return ((u64)b<<32) | (u64)b;
}
__device__ __forceinline__ float rcpf(float x){ float r; asm("rcp.approx.f32 %0,%1;" : "=f"(r):"f"(x)); return r; }
__device__ __forceinline__ float ex2f(float x){ float r; asm("ex2.approx.f32 %0,%1;" : "=f"(r):"f"(x)); return r; }

__device__ __forceinline__ float gelu_f(float v){           // exact (cold paths)
    return 0.5f*v*(1.0f + erff(v*0.70710678118654752f));
}

// packed branch-free gelu; A&S 7.1.26 erf, abs err <= 1.5e-7
__device__ __forceinline__ u64 gelu2(u64 r2){
    u64 z2  = mul2(r2, dup2(0.70710678118654752f));
    u64 az2 = z2 & 0x7FFFFFFF7FFFFFFFULL;
    u64 w2  = fma2(az2, dup2(0.3275911f), dup2(1.0f));
    float wlo, whi; upk(w2, wlo, whi);
    u64 t2  = pk(rcpf(wlo), rcpf(whi));
    u64 zz2 = mul2(z2, z2);
    u64 ag2 = mul2(zz2, dup2(-1.4426950408889634f));
    float alo, ahi; upk(ag2, alo, ahi);
    u64 e2  = pk(ex2f(alo), ex2f(ahi));
    u64 s2  = fma2(t2, dup2(-1.061405429f), dup2(1.453152027f));
    s2 = fma2(s2, t2, dup2(-1.421413741f));
    s2 = fma2(s2, t2, dup2( 0.284496736f));
    s2 = fma2(s2, t2, dup2(-0.254829592f));
    s2 = mul2(s2, t2);                                   // -s
    u64 erfa2 = fma2(s2, e2, dup2(1.0f));
    u64 es2   = erfa2 | (z2 & 0x8000000080000000ULL);
    u64 hr2   = mul2(r2, dup2(0.5f));
    return fma2(hr2, es2, hr2);
}

// ---- float<->monotone-unsigned encoding for atomic max ----
__device__ __forceinline__ unsigned encf(float x){
    unsigned u = __float_as_uint(x);
    return (u & 0x80000000u) ? ~u : (u | 0x80000000u);
}
__device__ __forceinline__ float decf(unsigned e){
    return (e & 0x80000000u) ? __uint_as_float(e ^ 0x80000000u) : __uint_as_float(~e);
}

// one-shot weight transpose (all layers)
__global__ void k_transW(const float* __restrict__ qw, const float* __restrict__ kw,
                         const float* __restrict__ vw, const float* __restrict__ ow,
                         const float* __restrict__ f1w, const float* __restrict__ f2w){
    int i = blockIdx.x*blockDim.x + threadIdx.x;
    if (i < Ln*Dn*Dn){
        int l = i/(Dn*Dn), r = i%(Dn*Dn);
        int o = r/Dn, d = r%Dn;
        int dst = l*Dn*Dn + d*Dn + o;
        g_qwT[dst]=qw[i]; g_kwT[dst]=kw[i]; g_vwT[dst]=vw[i]; g_owT[dst]=ow[i];
    }
    if (i < Ln*FFn*Dn){
        int l = i/(FFn*Dn), r = i%(FFn*Dn);
        int o = r/Dn, d = r%Dn;            // f1w: [o=256][d=64]
        g_f1wT[l*FFn*Dn + d*FFn + o] = f1w[i];
        int o2 = r/FFn, d2 = r%FFn;        // f2w: [o=64][d=256]
        g_f2wT[l*FFn*Dn + d2*Dn + o2] = f2w[i];
    }
}

__global__ void k_binding(const float* __restrict__ x, const float* __restrict__ role,
                          const float* __restrict__ fw){
    int idx = blockIdx.x*blockDim.x + threadIdx.x;
    if (idx >= Bn*Cn*Dn) return;
    int dd = idx & 63;
    int bc = idx >> 6;
    int c  = bc & (Cn-1);
    float xl = log1pf(fmaxf(x[bc], 0.0f));
    g_h[idx] = role[c*Dn + dd] * gelu_f(xl * fw[dd]);
}

// coalesced transposed-weight qkv (weights via device symbols + layer index)
__global__ void k_qkv(int l, const float* __restrict__ qb,
                      const float* __restrict__ kb, const float* __restrict__ vb){
    __shared__ float hs[4][Dn];
    const float* qwT = g_qwT + l*Dn*Dn;
    const float* kwT = g_kwT + l*Dn*Dn;
    const float* vwT = g_vwT + l*Dn*Dn;
    int r0 = blockIdx.x*4;
    int t  = threadIdx.x;
    for (int i=t; i<4*Dn; i+=64) hs[i>>6][i&63] = g_h[r0*Dn + i];
    __syncthreads();
    int o = t;
    float bq=qb[o], bk=kb[o], bv=vb[o];
    float aq[4]={bq,bq,bq,bq}, ak[4]={bk,bk,bk,bk}, av[4]={bv,bv,bv,bv};
    for (int d=0; d<Dn; d++){
        float wq=qwT[d*Dn+o], wk2=kwT[d*Dn+o], wv=vwT[d*Dn+o];
        #pragma unroll
        for (int r=0;r<4;r++){
            float hh = hs[r][d];
            aq[r]=fmaf(wq ,hh,aq[r]);
            ak[r]=fmaf(wk2,hh,ak[r]);
            av[r]=fmaf(wv ,hh,av[r]);
        }
    }
    #pragma unroll
    for (int r=0;r<4;r++){
        g_q[(r0+r)*Dn+o]=aq[r];
        g_k[(r0+r)*Dn+o]=ak[r];
        g_v[(r0+r)*Dn+o]=av[r];
    }
}

// qp = q @ w1q.T + b1 (folded), kp = k @ w1k.T; also zeroes g_rowmax
__global__ void k_phead(const float* __restrict__ w1l, const float* __restrict__ b1l){
    __shared__ float qs[4][Dn], ks[4][Dn];
    int r0 = blockIdx.x*4;
    int t  = threadIdx.x;
    int gid = blockIdx.x*64 + t;
    if (gid < BHn*Cn) g_rowmax[gid] = 0u;
    for (int i=t;i<4*Dn;i+=64){ qs[i>>6][i&63]=g_q[r0*Dn+i]; ks[i>>6][i&63]=g_k[r0*Dn+i]; }
    __syncthreads();
    int o=t, hh=o>>4, ci=o&15;
    float wq[16], wk[16];
    #pragma unroll
    for (int e=0;e<16;e++){ wq[e]=w1l[ci*48+e]; wk[e]=w1l[ci*48+16+e]; }
    float bb = b1l[ci];
    #pragma unroll
    for (int r=0;r<4;r++){
        float aq=bb, ak=0.f;
        #pragma unroll
        for (int e=0;e<16;e++){
            aq = fmaf(qs[r][hh*16+e], wq[e], aq);
            ak = fmaf(ks[r][hh*16+e], wk[e], ak);
        }
        g_qp[(r0+r)*Dn+o]=aq;
        g_kp[(r0+r)*Dn+o]=ak;
    }
}

// hot loop: grid (C/32 j, C/32 i, B*H), 256 threads = 32 i x 8 j-groups (4 j each)
__global__ void __launch_bounds__(256) k_score(const float* __restrict__ w1l,
                                               const float* __restrict__ w2l,
                                               const float* __restrict__ b2l){
    __shared__ float qs [32][17];
    __shared__ float ks [32][17];
    __shared__ __align__(16) float qps[32][20];
    __shared__ float kps[32][17];
    __shared__ __align__(16) u64 k2t[16][18];
    __shared__ __align__(16) u64 kpt[16][18];
    __shared__ __align__(16) u64 wd [16][18];
    __shared__ u64 w2d[16];

    int bh = blockIdx.z; int b = bh>>2; int hh = bh&3;
    int i0 = blockIdx.y<<5, j0 = blockIdx.x<<5;
    int t  = threadIdx.x;

    {
        int t2 = t & 127;
        int row = t2 >> 2, q4 = t2 & 3;
        if (t < 128){
            int gidx = (b*Cn + i0 + row)*Dn + hh*16 + q4*4;
            float4 qv  = *(const float4*)(g_q  + gidx);
            float4 qpv = *(const float4*)(g_qp + gidx);
            qs[row][q4*4+0]=qv.x; qs[row][q4*4+1]=qv.y;
            qs[row][q4*4+2]=qv.z; qs[row][q4*4+3]=qv.w;
            *(float4*)&qps[row][q4*4] = qpv;
        } else {
            int gidx = (b*Cn + j0 + row)*Dn + hh*16 + q4*4;
            float4 kv  = *(const float4*)(g_k  + gidx);
            float4 kpv = *(const float4*)(g_kp + gidx);
            ks[row][q4*4+0]=kv.x; ks[row][q4*4+1]=kv.y;
            ks[row][q4*4+2]=kv.z; ks[row][q4*4+3]=kv.w;
            kps[row][q4*4+0]=kpv.x; kps[row][q4*4+1]=kpv.y;
            kps[row][q4*4+2]=kpv.z; kps[row][q4*4+3]=kpv.w;
        }
        int c = t>>4, e = t&15;
        float wv = w1l[c*48 + 32 + e];
        wd[c][e] = pk(wv, wv);
        if (t < 16) w2d[t] = pk(w2l[t], w2l[t]);
    }
    __syncthreads();
    {
        int e = t>>4, jp = t&15;
        k2t[e][jp] = pk(ks [2*jp][e], ks [2*jp+1][e]);
        kpt[e][jp] = pk(kps[2*jp][e], kps[2*jp+1][e]);
    }
    __syncthreads();

    int ti  = t>>3;
    int jpb = (t&7)*2;

    u64 pe0[16], pe1[16];
    #pragma unroll
    for (int e=0;e<16;e++){
        float qf = qs[ti][e];
        u64 q2 = pk(qf, qf);
        ulonglong2 kk = *(ulonglong2*)&k2t[e][jpb];
        pe0[e] = mul2(q2, kk.x);
        pe1[e] = mul2(q2, kk.y);
    }

    u64 acc0 = dup2(0.0f), acc1 = dup2(0.0f);
    #pragma unroll
    for (int c=0;c<16;c++){
        ulonglong2 kp2 = *(ulonglong2*)&kpt[c][jpb];
        float qpf = qps[ti][c];
        u64 qpd = pk(qpf, qpf);
        u64 r0 = add2(qpd, kp2.x);
        u64 r1 = add2(qpd, kp2.y);
        ulonglong2* wp = (ulonglong2*)&wd[c][0];
        #pragma unroll
        for (int e4=0;e4<8;e4++){
            ulonglong2 wv = wp[e4];
            r0 = fma2(wv.x, pe0[2*e4+0], r0);
            r1 = fma2(wv.x, pe1[2*e4+0], r1);
            r0 = fma2(wv.y, pe0[2*e4+1], r0);
            r1 = fma2(wv.y, pe1[2*e4+1], r1);
        }
        u64 w2c = w2d[c];
        acc0 = fma2(gelu2(r0), w2c, acc0);
        acc1 = fma2(gelu2(r1), w2c, acc1);
    }

    float b2 = __ldg(b2l);
    float a0,a1,a2,a3;
    upk(acc0, a0, a1); upk(acc1, a2, a3);
    float s0 = 0.25f*(a0+b2), s1 = 0.25f*(a1+b2);
    float s2 = 0.25f*(a2+b2), s3 = 0.25f*(a3+b2);
    size_t off = ((size_t)bh*Cn + (i0+ti))*Cn + j0 + jpb*2;
    *(float4*)(g_S + off) = make_float4(s0,s1,s2,s3);

    float m = fmaxf(fmaxf(s0,s1), fmaxf(s2,s3));
    m = fmaxf(m, __shfl_xor_sync(0xffffffffu, m, 1, 8));
    m = fmaxf(m, __shfl_xor_sync(0xffffffffu, m, 2, 8));
    m = fmaxf(m, __shfl_xor_sync(0xffffffffu, m, 4, 8));
    if ((t & 7) == 0) atomicMax(&g_rowmax[bh*Cn + i0 + ti], encf(m));
}

// softmax + A@V fused (single pass; max from g_rowmax): grid (C/64, B*H)
__global__ void __launch_bounds__(256) k_softav(){
    int bh=blockIdx.y, b=bh>>2, hh=bh&3;
    int i0=blockIdx.x<<6;
    int t=threadIdx.x, li=t>>2, g=t&3;
    const float* sr = g_S + ((size_t)bh*Cn + i0 + li)*Cn;
    float m = decf(g_rowmax[bh*Cn + i0 + li]);

    __shared__ float red[64][4];
    __shared__ float vt[64][16];
    __shared__ float et[64][65];
    float a0=0.f,a1=0.f,a2=0.f,a3=0.f, sacc=0.f;

    for (int jt=0;jt<Cn/64;jt++){
        __syncthreads();
        {
            int row=t>>2, qd=t&3;
            float4 vv = *(const float4*)(g_v + ((size_t)(b*Cn) + jt*64 + row)*Dn + hh*16 + qd*4);
            *(float4*)&vt[row][qd*4]=vv;
        }
        {
            const float* sp = sr + jt*64 + g*16;
            #pragma unroll
            for (int kk=0;kk<16;kk+=4){
                float4 s4=*(const float4*)(sp+kk);
                float e0=__expf(s4.x-m), e1=__expf(s4.y-m);
                float e2=__expf(s4.z-m), e3=__expf(s4.w-m);
                et[li][g*16+kk+0]=e0; et[li][g*16+kk+1]=e1;
                et[li][g*16+kk+2]=e2; et[li][g*16+kk+3]=e3;
                sacc += (e0+e1)+(e2+e3);
            }
        }
        __syncthreads();
        #pragma unroll 4
        for (int jj=0;jj<64;jj++){
            float ev=et[li][jj];
            float4 vv=*(const float4*)&vt[jj][g*4];
            a0=fmaf(ev,vv.x,a0); a1=fmaf(ev,vv.y,a1);
            a2=fmaf(ev,vv.z,a2); a3=fmaf(ev,vv.w,a3);
        }
    }
    __syncthreads();
    red[li][g]=sacc; __syncthreads();
    float inv = 1.0f/(red[li][0]+red[li][1]+red[li][2]+red[li][3]);
    *(float4*)(g_attn + ((size_t)(b*Cn)+i0+li)*Dn + hh*16 + g*4)
        = make_float4(a0*inv,a1*inv,a2*inv,a3*inv);
}

// linear(IN->64) + residual + LN; weights via device symbols + layer index
template<int IN>
__global__ void k_lin_res_ln(int l, const float* __restrict__ bias,
                             const float* __restrict__ gamma, const float* __restrict__ beta){
    __shared__ float xs[4][IN];
    __shared__ float vals[4][64];
    __shared__ float stats[4][2];
    const float* WT = (IN==64) ? (g_owT + l*Dn*Dn) : (g_f2wT + l*FFn*Dn);
    int r0=blockIdx.x*4, t=threadIdx.x;
    const float* src = (IN==64)? g_attn : g_ff;
    for (int i=t;i<4*IN;i+=64) xs[i/IN][i%IN] = src[r0*IN+i];
    __syncthreads();
    int o=t;
    float bb=bias[o];
    float acc[4]={bb,bb,bb,bb};
    for (int d=0;d<IN;d++){
        float w=WT[d*Dn+o];
        #pragma unroll
        for (int r=0;r<4;r++) acc[r]=fmaf(w,xs[r][d],acc[r]);
    }
    float val[4];
    #pragma unroll
    for (int r=0;r<4;r++){ val[r]=acc[r]+g_h[(r0+r)*Dn+o]; vals[r][o]=val[r]; }
    __syncthreads();
    int wr=t>>5, lane=t&31;
    #pragma unroll
    for (int rr2=0; rr2<2; rr2++){
        int rrow = wr*2+rr2;
        float v1=vals[rrow][lane], v2=vals[rrow][lane+32];
        float s=v1+v2, q=fmaf(v1,v1,v2*v2);
        #pragma unroll
        for (int off2=16; off2; off2>>=1){
            s += __shfl_down_sync(0xffffffffu, s, off2);
            q += __shfl_down_sync(0xffffffffu, q, off2);
        }
        if (lane==0){
            float mean=s*(1.0f/64.0f);
            float var = q*(1.0f/64.0f) - mean*mean;
            stats[rrow][0]=mean; stats[rrow][1]=rsqrtf(var+1e-5f);
        }
    }
    __syncthreads();
    float gm=gamma[o], bt=beta[o];
    #pragma unroll
    for (int r=0;r<4;r++)
        g_h[(r0+r)*Dn+o] = (val[r]-stats[r][0])*stats[r][1]*gm + bt;
}

// FFN1; weight via device symbol + layer index
__global__ void k_ffn1(int l, const float* __restrict__ bias){
    __shared__ float hs[4][Dn];
    const float* WT = g_f1wT + l*FFn*Dn;
    int r0=blockIdx.x*4, t=threadIdx.x;
    hs[t>>6][t&63]=g_h[r0*Dn+t];
    __syncthreads();
    int o=t;
    float bb=bias[o];
    float acc[4]={bb,bb,bb,bb};
    for (int d=0;d<Dn;d++){
        float w=WT[d*FFn+o];
        #pragma unroll
        for (int r=0;r<4;r++) acc[r]=fmaf(w,hs[r][d],acc[r]);
    }
    #pragma unroll
    for (int r=0;r<4;r++) g_ff[(r0+r)*FFn+o]=gelu_f(acc[r]);
}

__global__ void __launch_bounds__(256) k_readout(const float* __restrict__ tq,
        const float* __restrict__ hw, const float* __restrict__ hb, float* __restrict__ out){
    int b=blockIdx.x, t=threadIdx.x;
    __shared__ float ssm[Cn];
    __shared__ float tqs[Dn];
    __shared__ float red[256];
    __shared__ float pool[4][64];
    if (t<64) tqs[t]=tq[t];
    __syncthreads();
    for (int c=t;c<Cn;c+=256){
        const float* hr=g_h+((size_t)b*Cn+c)*Dn;
        float a=0.f;
        #pragma unroll
        for (int d=0;d<Dn;d++) a=fmaf(hr[d],tqs[d],a);
        ssm[c]=a*0.125f;
    }
    __syncthreads();
    float m=-3e38f;
    for (int c=t;c<Cn;c+=256) m=fmaxf(m,ssm[c]);
    red[t]=m; __syncthreads();
    for (int s2=128;s2;s2>>=1){ if(t<s2) red[t]=fmaxf(red[t],red[t+s2]); __syncthreads(); }
    m=red[0]; __syncthreads();
    float sacc=0.f;
    for (int c=t;c<Cn;c+=256){ float e=__expf(ssm[c]-m); ssm[c]=e; sacc+=e; }
    red[t]=sacc; __syncthreads();
    for (int s2=128;s2;s2>>=1){ if(t<s2) red[t]+=red[t+s2]; __syncthreads(); }
    float stot=red[0];
    __syncthreads();
    int dd=t&63, cg=t>>6;
    float acc=0.f;
    for (int c=cg*512; c<cg*512+512; c++)
        acc=fmaf(ssm[c], g_h[((size_t)b*Cn+c)*Dn+dd], acc);
    pool[cg][dd]=acc; __syncthreads();
    if (t<64) red[t]=(pool[0][t]+pool[1][t]+pool[2][t]+pool[3][t])/stot;
    __syncthreads();
    if (t<OUTn){
        float a=hb[t];
        #pragma unroll
        for (int d=0;d<Dn;d++) a=fmaf(red[d],hw[t*Dn+d],a);
        out[b*OUTn+t]=a;
    }
}

extern "C" void kernel_launch(void* const* d_in, const int* in_sizes, int n_in,
                              void* d_out, int out_size){
    (void)in_sizes; (void)n_in; (void)out_size;
    const float* x   =(const float*)d_in[0];
    const float* role=(const float*)d_in[1];
    const float* fw  =(const float*)d_in[2];
    const float* qw  =(const float*)d_in[3];  const float* qb =(const float*)d_in[4];
    const float* kw  =(const float*)d_in[5];  const float* kb =(const float*)d_in[6];
    const float* vw  =(const float*)d_in[7];  const float* vb =(const float*)d_in[8];
    const float* w1  =(const float*)d_in[9];  const float* b1 =(const float*)d_in[10];
    const float* w2  =(const float*)d_in[11]; const float* b2 =(const float*)d_in[12];
    const float* ow  =(const float*)d_in[13]; const float* ob =(const float*)d_in[14];
    const float* l1g =(const float*)d_in[15]; const float* l1b=(const float*)d_in[16];
    const float* f1w =(const float*)d_in[17]; const float* f1b=(const float*)d_in[18];
    const float* f2w =(const float*)d_in[19]; const float* f2b=(const float*)d_in[20];
    const float* l2g =(const float*)d_in[21]; const float* l2b=(const float*)d_in[22];
    const float* tq  =(const float*)d_in[23];
    const float* hw  =(const float*)d_in[24]; const float* hb =(const float*)d_in[25];
    float* out = (float*)d_out;

    int rows = Bn*Cn;
    k_transW<<<(Ln*FFn*Dn+255)/256,256>>>(qw,kw,vw,ow,f1w,f2w);
    k_binding<<<(Bn*Cn*Dn+255)/256,256>>>(x, role, fw);
    for (int l=0; l<Ln; l++){
        k_qkv  <<<rows/4,64>>>(l, qb+l*Dn, kb+l*Dn, vb+l*Dn);
        k_phead<<<rows/4,64>>>(w1+l*16*48, b1+l*16);
        dim3 gs(Cn/32, Cn/32, BHn);
        k_score<<<gs,256>>>(w1+l*16*48, w2+l*16, b2+l);
        dim3 ga(Cn/64, BHn);
        k_softav<<<ga,256>>>();
        k_lin_res_ln<64> <<<rows/4,64>>>(l, ob+l*Dn, l1g+l*Dn, l1b+l*Dn);
        k_ffn1<<<rows/4,256>>>(l, f1b+l*FFn);
        k_lin_res_ln<256><<<rows/4,64>>>(l, f2b+l*Dn, l2g+l*Dn, l2b+l*Dn);
    }
    k_readout<<<Bn,256>>>(tq, hw, hb, out);
}

// round 11
// speedup vs baseline: 1.5753x; 1.0231x over previous
#include <cuda_runtime.h>
#include <math.h>

#define Bn 8
#define Cn 2048
#define Dn 64
#define Hn 4
#define Ln 3
#define FFn 256
#define OUTn 10
#define BHn (Bn*Hn)

typedef unsigned long long u64;

__device__ float g_h   [Bn*Cn*Dn];
__device__ float g_q   [Bn*Cn*Dn];
__device__ float g_k   [Bn*Cn*Dn];
__device__ float g_v   [Bn*Cn*Dn];
__device__ float g_qp  [Bn*Cn*Dn];
__device__ float g_kp  [Bn*Cn*Dn];
__device__ float g_attn[Bn*Cn*Dn];
__device__ float g_ff  [Bn*Cn*FFn];
__device__ unsigned g_rowmax[BHn*Cn];
__device__ float g_S   [(size_t)BHn*Cn*Cn];

// transposed weights (built once per call by k_transW)
__device__ float g_qwT [Ln*Dn*Dn];
__device__ float g_kwT [Ln*Dn*Dn];
__device__ float g_vwT [Ln*Dn*Dn];
__device__ float g_owT [Ln*Dn*Dn];
__device__ float g_f1wT[Ln*Dn*FFn];
__device__ float g_f2wT[Ln*FFn*Dn];

// ---- f32x2 packed helpers (sm_103a) ----
__device__ __forceinline__ u64 pk(float lo, float hi){
    u64 r; asm("mov.b64 %0,{%1,%2};" : "=l"(r) : "f"(lo), "f"(hi)); return r;
}
__device__ __forceinline__ void upk(u64 v, float& lo, float& hi){
    asm("mov.b64 {%0,%1},%2;" : "=f"(lo), "=f"(hi) : "l"(v));
}
__device__ __forceinline__ u64 mul2(u64 a, u64 b){
    u64 r; asm("mul.rn.f32x2 %0,%1,%2;" : "=l"(r) : "l"(a), "l"(b)); return r;
}
__device__ __forceinline__ u64 fma2(u64 a, u64 b, u64 c){
    u64 r; asm("fma.rn.f32x2 %0,%1,%2,%3;" : "=l"(r) : "l"(a), "l"(b), "l"(c)); return r;
}
__device__ __forceinline__ u64 add2(u64 a, u64 b){
    u64 r; asm("add.rn.f32x2 %0,%1,%2;" : "=l"(r) : "l"(a), "l"(b)); return r;
}
__device__ __forceinline__ u64 dup2(float v){
    unsigned b = __float_as_uint(v);
    return ((u64)b<<32) | (u64)b;
}
__device__ __forceinline__ float rcpf(float x){ float r; asm("rcp.approx.f32 %0,%1;" : "=f"(r):"f"(x)); return r; }
__device__ __forceinline__ float ex2f(float x){ float r; asm("ex2.approx.f32 %0,%1;" : "=f"(r):"f"(x)); return r; }

// scalar fast gelu: A&S 7.1.25 3-term erf (|erf err| <= 2.5e-5)
__device__ __forceinline__ float gelu_fast(float r){
    float z  = r * 0.70710678118654752f;
    float az = fabsf(z);
    float w  = fmaf(0.47047f, az, 1.0f);
    float t  = rcpf(w);
    float ex = ex2f(-1.4426950408889634f * z * z);
    float u  = fmaf(t, -0.7478556f, 0.0958798f);
    u = fmaf(u, t, -0.3480242f);
    u = u * t;                            // u = -s(t)
    float erfa = fmaf(u, ex, 1.0f);       // erf(|z|)
    float es   = copysignf(erfa, z);
    float hr   = 0.5f*r;
    return fmaf(hr, es, hr);
}

// packed gelu, 3-term erf; returns r*(1+erf(r/sqrt2)) = 2*gelu(r)
__device__ __forceinline__ u64 gelu2x(u64 r2){
    u64 z2  = mul2(r2, dup2(0.70710678118654752f));
    u64 az2 = z2 & 0x7FFFFFFF7FFFFFFFULL;
    u64 w2  = fma2(az2, dup2(0.47047f), dup2(1.0f));
    float wlo, whi; upk(w2, wlo, whi);
    u64 t2  = pk(rcpf(wlo), rcpf(whi));
    u64 zz2 = mul2(z2, z2);
    u64 ag2 = mul2(zz2, dup2(-1.4426950408889634f));
    float alo, ahi; upk(ag2, alo, ahi);
    u64 e2  = pk(ex2f(alo), ex2f(ahi));
    u64 u2  = fma2(t2, dup2(-0.7478556f), dup2(0.0958798f));
    u2 = fma2(u2, t2, dup2(-0.3480242f));
    u2 = mul2(u2, t2);                                   // -s
    u64 erfa2 = fma2(u2, e2, dup2(1.0f));                // erf(|z|) in [0,1)
    u64 es2   = erfa2 | (z2 & 0x8000000080000000ULL);    // copysign from z
    return fma2(r2, es2, r2);                            // r*(1+erf)
}

// ---- float<->monotone-unsigned encoding for atomic max ----
__device__ __forceinline__ unsigned encf(float x){
    unsigned u = __float_as_uint(x);
    return (u & 0x80000000u) ? ~u : (u | 0x80000000u);
}
__device__ __forceinline__ float decf(unsigned e){
    return (e & 0x80000000u) ? __uint_as_float(e ^ 0x80000000u) : __uint_as_float(~e);
}

// one-shot weight transpose (all layers)
__global__ void k_transW(const float* __restrict__ qw, const float* __restrict__ kw,
                         const float* __restrict__ vw, const float* __restrict__ ow,
                         const float* __restrict__ f1w, const float* __restrict__ f2w){
    int i = blockIdx.x*blockDim.x + threadIdx.x;
    if (i < Ln*Dn*Dn){
        int l = i/(Dn*Dn), r = i%(Dn*Dn);
        int o = r/Dn, d = r%Dn;
        int dst = l*Dn*Dn + d*Dn + o;
        g_qwT[dst]=qw[i]; g_kwT[dst]=kw[i]; g_vwT[dst]=vw[i]; g_owT[dst]=ow[i];
    }
    if (i < Ln*FFn*Dn){
        int l = i/(FFn*Dn), r = i%(FFn*Dn);
        int o = r/Dn, d = r%Dn;
        g_f1wT[l*FFn*Dn + d*FFn + o] = f1w[i];
        int o2 = r/FFn, d2 = r%FFn;
        g_f2wT[l*FFn*Dn + d2*Dn + o2] = f2w[i];
    }
}

__global__ void k_binding(const float* __restrict__ x, const float* __restrict__ role,
                          const float* __restrict__ fw){
    int idx = blockIdx.x*blockDim.x + threadIdx.x;
    if (idx >= Bn*Cn*Dn) return;
    int dd = idx & 63;
    int bc = idx >> 6;
    int c  = bc & (Cn-1);
    float xl = log1pf(fmaxf(x[bc], 0.0f));
    g_h[idx] = role[c*Dn + dd] * gelu_fast(xl * fw[dd]);
}

__global__ void k_qkv(int l, const float* __restrict__ qb,
                      const float* __restrict__ kb, const float* __restrict__ vb){
    __shared__ float hs[4][Dn];
    const float* qwT = g_qwT + l*Dn*Dn;
    const float* kwT = g_kwT + l*Dn*Dn;
    const float* vwT = g_vwT + l*Dn*Dn;
    int r0 = blockIdx.x*4;
    int t  = threadIdx.x;
    for (int i=t; i<4*Dn; i+=64) hs[i>>6][i&63] = g_h[r0*Dn + i];
    __syncthreads();
    int o = t;
    float bq=qb[o], bk=kb[o], bv=vb[o];
    float aq[4]={bq,bq,bq,bq}, ak[4]={bk,bk,bk,bk}, av[4]={bv,bv,bv,bv};
    for (int d=0; d<Dn; d++){
        float wq=qwT[d*Dn+o], wk2=kwT[d*Dn+o], wv=vwT[d*Dn+o];
        #pragma unroll
        for (int r=0;r<4;r++){
            float hh = hs[r][d];
            aq[r]=fmaf(wq ,hh,aq[r]);
            ak[r]=fmaf(wk2,hh,ak[r]);
            av[r]=fmaf(wv ,hh,av[r]);
        }
    }
    #pragma unroll
    for (int r=0;r<4;r++){
        g_q[(r0+r)*Dn+o]=aq[r];
        g_k[(r0+r)*Dn+o]=ak[r];
        g_v[(r0+r)*Dn+o]=av[r];
    }
}

// qp = q @ w1q.T + b1 (folded), kp = k @ w1k.T; also zeroes g_rowmax
__global__ void k_phead(const float* __restrict__ w1l, const float* __restrict__ b1l){
    __shared__ float qs[4][Dn], ks[4][Dn];
    int r0 = blockIdx.x*4;
    int t  = threadIdx.x;
    int gid = blockIdx.x*64 + t;
    if (gid < BHn*Cn) g_rowmax[gid] = 0u;
    for (int i=t;i<4*Dn;i+=64){ qs[i>>6][i&63]=g_q[r0*Dn+i]; ks[i>>6][i&63]=g_k[r0*Dn+i]; }
    __syncthreads();
    int o=t, hh=o>>4, ci=o&15;
    float wq[16], wk[16];
    #pragma unroll
    for (int e=0;e<16;e++){ wq[e]=w1l[ci*48+e]; wk[e]=w1l[ci*48+16+e]; }
    float bb = b1l[ci];
    #pragma unroll
    for (int r=0;r<4;r++){
        float aq=bb, ak=0.f;
        #pragma unroll
        for (int e=0;e<16;e++){
            aq = fmaf(qs[r][hh*16+e], wq[e], aq);
            ak = fmaf(ks[r][hh*16+e], wk[e], ak);
        }
        g_qp[(r0+r)*Dn+o]=aq;
        g_kp[(r0+r)*Dn+o]=ak;
    }
}

// hot loop: grid (C/32 j, C/32 i, B*H), 256 threads = 32 i x 8 j-groups (4 j each)
__global__ void __launch_bounds__(256) k_score(const float* __restrict__ w1l,
                                               const float* __restrict__ w2l,
                                               const float* __restrict__ b2l){
    __shared__ float qs [32][17];
    __shared__ float ks [32][17];
    __shared__ __align__(16) float qps[32][20];
    __shared__ float kps[32][17];
    __shared__ __align__(16) u64 k2t[16][18];
    __shared__ __align__(16) u64 kpt[16][18];
    __shared__ __align__(16) u64 wd [16][18];
    __shared__ u64 w2d[16];    // 0.125 * w2 (folds gelu 0.5 and score 0.25)

    int bh = blockIdx.z; int b = bh>>2; int hh = bh&3;
    int i0 = blockIdx.y<<5, j0 = blockIdx.x<<5;
    int t  = threadIdx.x;

    {
        int t2 = t & 127;
        int row = t2 >> 2, q4 = t2 & 3;
        if (t < 128){
            int gidx = (b*Cn + i0 + row)*Dn + hh*16 + q4*4;
            float4 qv  = *(const float4*)(g_q  + gidx);
            float4 qpv = *(const float4*)(g_qp + gidx);
            qs[row][q4*4+0]=qv.x; qs[row][q4*4+1]=qv.y;
            qs[row][q4*4+2]=qv.z; qs[row][q4*4+3]=qv.w;
            *(float4*)&qps[row][q4*4] = qpv;
        } else {
            int gidx = (b*Cn + j0 + row)*Dn + hh*16 + q4*4;
            float4 kv  = *(const float4*)(g_k  + gidx);
            float4 kpv = *(const float4*)(g_kp + gidx);
            ks[row][q4*4+0]=kv.x; ks[row][q4*4+1]=kv.y;
            ks[row][q4*4+2]=kv.z; ks[row][q4*4+3]=kv.w;
            kps[row][q4*4+0]=kpv.x; kps[row][q4*4+1]=kpv.y;
            kps[row][q4*4+2]=kpv.z; kps[row][q4*4+3]=kpv.w;
        }
        int c = t>>4, e = t&15;
        float wv = w1l[c*48 + 32 + e];
        wd[c][e] = pk(wv, wv);
        if (t < 16){ float w8 = 0.125f*w2l[t]; w2d[t] = pk(w8, w8); }
    }
    __syncthreads();
    {
        int e = t>>4, jp = t&15;
        k2t[e][jp] = pk(ks [2*jp][e], ks [2*jp+1][e]);
        kpt[e][jp] = pk(kps[2*jp][e], kps[2*jp+1][e]);
    }
    __syncthreads();

    int ti  = t>>3;
    int jpb = (t&7)*2;

    u64 pe0[16], pe1[16];
    #pragma unroll
    for (int e=0;e<16;e++){
        float qf = qs[ti][e];
        u64 q2 = pk(qf, qf);
        ulonglong2 kk = *(ulonglong2*)&k2t[e][jpb];
        pe0[e] = mul2(q2, kk.x);
        pe1[e] = mul2(q2, kk.y);
    }

    u64 acc0 = dup2(0.0f), acc1 = dup2(0.0f);
    #pragma unroll
    for (int c=0;c<16;c++){
        ulonglong2 kp2 = *(ulonglong2*)&kpt[c][jpb];
        float qpf = qps[ti][c];
        u64 qpd = pk(qpf, qpf);
        u64 r0 = add2(qpd, kp2.x);
        u64 r1 = add2(qpd, kp2.y);
        ulonglong2* wp = (ulonglong2*)&wd[c][0];
        #pragma unroll
        for (int e4=0;e4<8;e4++){
            ulonglong2 wv = wp[e4];
            r0 = fma2(wv.x, pe0[2*e4+0], r0);
            r1 = fma2(wv.x, pe1[2*e4+0], r1);
            r0 = fma2(wv.y, pe0[2*e4+1], r0);
            r1 = fma2(wv.y, pe1[2*e4+1], r1);
        }
        u64 w2c = w2d[c];
        acc0 = fma2(gelu2x(r0), w2c, acc0);
        acc1 = fma2(gelu2x(r1), w2c, acc1);
    }

    float b2q = 0.25f * __ldg(b2l);
    float a0,a1,a2,a3;
    upk(acc0, a0, a1); upk(acc1, a2, a3);
    float s0 = a0+b2q, s1 = a1+b2q;
    float s2 = a2+b2q, s3 = a3+b2q;
    size_t off = ((size_t)bh*Cn + (i0+ti))*Cn + j0 + jpb*2;
    *(float4*)(g_S + off) = make_float4(s0,s1,s2,s3);

    float m = fmaxf(fmaxf(s0,s1), fmaxf(s2,s3));
    m = fmaxf(m, __shfl_xor_sync(0xffffffffu, m, 1, 8));
    m = fmaxf(m, __shfl_xor_sync(0xffffffffu, m, 2, 8));
    m = fmaxf(m, __shfl_xor_sync(0xffffffffu, m, 4, 8));
    if ((t & 7) == 0) atomicMax(&g_rowmax[bh*Cn + i0 + ti], encf(m));
}

// softmax + A@V fused (single pass; max from g_rowmax): grid (C/64, B*H)
__global__ void __launch_bounds__(256) k_softav(){
    int bh=blockIdx.y, b=bh>>2, hh=bh&3;
    int i0=blockIdx.x<<6;
    int t=threadIdx.x, li=t>>2, g=t&3;
    const float* sr = g_S + ((size_t)bh*Cn + i0 + li)*Cn;
    float m = decf(g_rowmax[bh*Cn + i0 + li]);

    __shared__ float red[64][4];
    __shared__ float vt[64][16];
    __shared__ float et[64][65];
    float a0=0.f,a1=0.f,a2=0.f,a3=0.f, sacc=0.f;

    for (int jt=0;jt<Cn/64;jt++){
        __syncthreads();
        {
            int row=t>>2, qd=t&3;
            float4 vv = *(const float4*)(g_v + ((size_t)(b*Cn) + jt*64 + row)*Dn + hh*16 + qd*4);
            *(float4*)&vt[row][qd*4]=vv;
        }
        {
            const float* sp = sr + jt*64 + g*16;
            #pragma unroll
            for (int kk=0;kk<16;kk+=4){
                float4 s4=*(const float4*)(sp+kk);
                float e0=__expf(s4.x-m), e1=__expf(s4.y-m);
                float e2=__expf(s4.z-m), e3=__expf(s4.w-m);
                et[li][g*16+kk+0]=e0; et[li][g*16+kk+1]=e1;
                et[li][g*16+kk+2]=e2; et[li][g*16+kk+3]=e3;
                sacc += (e0+e1)+(e2+e3);
            }
        }
        __syncthreads();
        #pragma unroll 4
        for (int jj=0;jj<64;jj++){
            float ev=et[li][jj];
            float4 vv=*(const float4*)&vt[jj][g*4];
            a0=fmaf(ev,vv.x,a0); a1=fmaf(ev,vv.y,a1);
            a2=fmaf(ev,vv.z,a2); a3=fmaf(ev,vv.w,a3);
        }
    }
    __syncthreads();
    red[li][g]=sacc; __syncthreads();
    float inv = 1.0f/(red[li][0]+red[li][1]+red[li][2]+red[li][3]);
    *(float4*)(g_attn + ((size_t)(b*Cn)+i0+li)*Dn + hh*16 + g*4)
        = make_float4(a0*inv,a1*inv,a2*inv,a3*inv);
}

// linear(IN->64) + residual + LN; weights via device symbols + layer index
template<int IN>
__global__ void k_lin_res_ln(int l, const float* __restrict__ bias,
                             const float* __restrict__ gamma, const float* __restrict__ beta){
    __shared__ float xs[4][IN];
    __shared__ float vals[4][64];
    __shared__ float stats[4][2];
    const float* WT = (IN==64) ? (g_owT + l*Dn*Dn) : (g_f2wT + l*FFn*Dn);
    int r0=blockIdx.x*4, t=threadIdx.x;
    const float* src = (IN==64)? g_attn : g_ff;
    for (int i=t;i<4*IN;i+=64) xs[i/IN][i%IN] = src[r0*IN+i];
    __syncthreads();
    int o=t;
    float bb=bias[o];
    float acc[4]={bb,bb,bb,bb};
    for (int d=0;d<IN;d++){
        float w=WT[d*Dn+o];
        #pragma unroll
        for (int r=0;r<4;r++) acc[r]=fmaf(w,xs[r][d],acc[r]);
    }
    float val[4];
    #pragma unroll
    for (int r=0;r<4;r++){ val[r]=acc[r]+g_h[(r0+r)*Dn+o]; vals[r][o]=val[r]; }
    __syncthreads();
    int wr=t>>5, lane=t&31;
    #pragma unroll
    for (int rr2=0; rr2<2; rr2++){
        int rrow = wr*2+rr2;
        float v1=vals[rrow][lane], v2=vals[rrow][lane+32];
        float s=v1+v2, q=fmaf(v1,v1,v2*v2);
        #pragma unroll
        for (int off2=16; off2; off2>>=1){
            s += __shfl_down_sync(0xffffffffu, s, off2);
            q += __shfl_down_sync(0xffffffffu, q, off2);
        }
        if (lane==0){
            float mean=s*(1.0f/64.0f);
            float var = q*(1.0f/64.0f) - mean*mean;
            stats[rrow][0]=mean; stats[rrow][1]=rsqrtf(var+1e-5f);
        }
    }
    __syncthreads();
    float gm=gamma[o], bt=beta[o];
    #pragma unroll
    for (int r=0;r<4;r++)
        g_h[(r0+r)*Dn+o] = (val[r]-stats[r][0])*stats[r][1]*gm + bt;
}

// FFN1; weight via device symbol + layer index
__global__ void k_ffn1(int l, const float* __restrict__ bias){
    __shared__ float hs[4][Dn];
    const float* WT = g_f1wT + l*FFn*Dn;
    int r0=blockIdx.x*4, t=threadIdx.x;
    hs[t>>6][t&63]=g_h[r0*Dn+t];
    __syncthreads();
    int o=t;
    float bb=bias[o];
    float acc[4]={bb,bb,bb,bb};
    for (int d=0;d<Dn;d++){
        float w=WT[d*FFn+o];
        #pragma unroll
        for (int r=0;r<4;r++) acc[r]=fmaf(w,hs[r][d],acc[r]);
    }
    #pragma unroll
    for (int r=0;r<4;r++) g_ff[(r0+r)*FFn+o]=gelu_fast(acc[r]);
}

__global__ void __launch_bounds__(256) k_readout(const float* __restrict__ tq,
        const float* __restrict__ hw, const float* __restrict__ hb, float* __restrict__ out){
    int b=blockIdx.x, t=threadIdx.x;
    __shared__ float ssm[Cn];
    __shared__ float tqs[Dn];
    __shared__ float red[256];
    __shared__ float pool[4][64];
    if (t<64) tqs[t]=tq[t];
    __syncthreads();
    for (int c=t;c<Cn;c+=256){
        const float* hr=g_h+((size_t)b*Cn+c)*Dn;
        float a=0.f;
        #pragma unroll
        for (int d=0;d<Dn;d++) a=fmaf(hr[d],tqs[d],a);
        ssm[c]=a*0.125f;
    }
    __syncthreads();
    float m=-3e38f;
    for (int c=t;c<Cn;c+=256) m=fmaxf(m,ssm[c]);
    red[t]=m; __syncthreads();
    for (int s2=128;s2;s2>>=1){ if(t<s2) red[t]=fmaxf(red[t],red[t+s2]); __syncthreads(); }
    m=red[0]; __syncthreads();
    float sacc=0.f;
    for (int c=t;c<Cn;c+=256){ float e=__expf(ssm[c]-m); ssm[c]=e; sacc+=e; }
    red[t]=sacc; __syncthreads();
    for (int s2=128;s2;s2>>=1){ if(t<s2) red[t]+=red[t+s2]; __syncthreads(); }
    float stot=red[0];
    __syncthreads();
    int dd=t&63, cg=t>>6;
    float acc=0.f;
    for (int c=cg*512; c<cg*512+512; c++)
        acc=fmaf(ssm[c], g_h[((size_t)b*Cn+c)*Dn+dd], acc);
    pool[cg][dd]=acc; __syncthreads();
    if (t<64) red[t]=(pool[0][t]+pool[1][t]+pool[2][t]+pool[3][t])/stot;
    __syncthreads();
    if (t<OUTn){
        float a=hb[t];
        #pragma unroll
        for (int d=0;d<Dn;d++) a=fmaf(red[d],hw[t*Dn+d],a);
        out[b*OUTn+t]=a;
    }
}

extern "C" void kernel_launch(void* const* d_in, const int* in_sizes, int n_in,
                              void* d_out, int out_size){
    (void)in_sizes; (void)n_in; (void)out_size;
    const float* x   =(const float*)d_in[0];
    const float* role=(const float*)d_in[1];
    const float* fw  =(const float*)d_in[2];
    const float* qw  =(const float*)d_in[3];  const float* qb =(const float*)d_in[4];
    const float* kw  =(const float*)d_in[5];  const float* kb =(const float*)d_in[6];
    const float* vw  =(const float*)d_in[7];  const float* vb =(const float*)d_in[8];
    const float* w1  =(const float*)d_in[9];  const float* b1 =(const float*)d_in[10];
    const float* w2  =(const float*)d_in[11]; const float* b2 =(const float*)d_in[12];
    const float* ow  =(const float*)d_in[13]; const float* ob =(const float*)d_in[14];
    const float* l1g =(const float*)d_in[15]; const float* l1b=(const float*)d_in[16];
    const float* f1w =(const float*)d_in[17]; const float* f1b=(const float*)d_in[18];
    const float* f2w =(const float*)d_in[19]; const float* f2b=(const float*)d_in[20];
    const float* l2g =(const float*)d_in[21]; const float* l2b=(const float*)d_in[22];
    const float* tq  =(const float*)d_in[23];
    const float* hw  =(const float*)d_in[24]; const float* hb =(const float*)d_in[25];
    float* out = (float*)d_out;

    int rows = Bn*Cn;
    k_transW<<<(Ln*FFn*Dn+255)/256,256>>>(qw,kw,vw,ow,f1w,f2w);
    k_binding<<<(Bn*Cn*Dn+255)/256,256>>>(x, role, fw);
    for (int l=0; l<Ln; l++){
        k_qkv  <<<rows/4,64>>>(l, qb+l*Dn, kb+l*Dn, vb+l*Dn);
        k_phead<<<rows/4,64>>>(w1+l*16*48, b1+l*16);
        dim3 gs(Cn/32, Cn/32, BHn);
        k_score<<<gs,256>>>(w1+l*16*48, w2+l*16, b2+l);
        dim3 ga(Cn/64, BHn);
        k_softav<<<ga,256>>>();
        k_lin_res_ln<64> <<<rows/4,64>>>(l, ob+l*Dn, l1g+l*Dn, l1b+l*Dn);
        k_ffn1<<<rows/4,256>>>(l, f1b+l*FFn);
        k_lin_res_ln<256><<<rows/4,64>>>(l, f2b+l*Dn, l2g+l*Dn, l2b+l*Dn);
    }
    k_readout<<<Bn,256>>>(tq, hw, hb, out);
}